// round 1
// baseline (speedup 1.0000x reference)
#include <cuda_runtime.h>

// HistogramLayer inference: bias[b] = prod_d hist_probs[bin(b,d), d]
//   hist_probs[j,d] = freq[j,d] / sum_j freq[j,d]
//   bin(b,d) = clip(searchsorted_right(edges[:,d], x) - 1, 0, 7)
//
// Edges are base=linspace(-4,4,9) times a positive per-feature scale, so
// edges[5][d] == scale_d exactly. We compute an arithmetic candidate bin
// t = clamp(floor(x/s + 4), 0, 7) (within +-1 of truth for any fp rounding)
// and then apply an EXACT fixup against the stored fp32 edge values:
//   b = t + (x >= e[t+1]) - (x < e[t])
// with sentinels e[0+]->-inf at t=0 and e[8]->+inf at t=7 so no extra
// range predicates are needed. This reproduces reference comparison
// semantics bit-exactly, including exact-tie cases.

#define D    16
#define NB   8
#define TPB  256
#define RPT  8

__global__ __launch_bounds__(TPB, 4)
void hist_kernel(const float* __restrict__ inp,
                 const float* __restrict__ freq,
                 const float* __restrict__ edges,
                 float* __restrict__ out, int nrows)
{
    __shared__ float2 s_ep[D * NB];        // (e_t | -inf, e_{t+1} | +inf) per (d,t)
    __shared__ float  s_p [D * NB];        // hist_probs transposed: [d][bin]
    __shared__ float  s_a [D];             // 1 / scale_d
    __shared__ float  s_e [(NB + 1) * D];  // raw edges [j][d]

    const int tid = threadIdx.x;
    if (tid < (NB + 1) * D) s_e[tid] = edges[tid];
    __syncthreads();

    if (tid < D) {
        const int d = tid;
        float ssum = 0.f;
        #pragma unroll
        for (int b = 0; b < NB; ++b) ssum += freq[b * D + d];
        const float inv = 1.0f / ssum;
        #pragma unroll
        for (int b = 0; b < NB; ++b) s_p[d * NB + b] = freq[b * D + d] * inv;

        const float pinf = __int_as_float(0x7f800000);
        #pragma unroll
        for (int t = 0; t < NB; ++t) {
            const float lo = (t == 0)      ? -pinf : s_e[t * D + d];
            const float hi = (t == NB - 1) ?  pinf : s_e[(t + 1) * D + d];
            s_ep[d * NB + t] = make_float2(lo, hi);
        }
        // base[5] == 1.0f exactly, so edges[5][d] == scale_d bit-exactly.
        s_a[d] = 1.0f / s_e[5 * D + d];
    }
    __syncthreads();

    const long long base = (long long)blockIdx.x * (TPB * RPT) + tid;

    #pragma unroll 1
    for (int r = 0; r < RPT; ++r) {
        const long long row = base + (long long)r * TPB;
        if (row >= nrows) break;

        const float4* p = reinterpret_cast<const float4*>(inp) + row * 4;
        const float4 v0 = p[0], v1 = p[1], v2 = p[2], v3 = p[3];
        const float xs[D] = {v0.x, v0.y, v0.z, v0.w,
                             v1.x, v1.y, v1.z, v1.w,
                             v2.x, v2.y, v2.z, v2.w,
                             v3.x, v3.y, v3.z, v3.w};

        float pr0 = 1.0f, pr1 = 1.0f;
        #pragma unroll
        for (int d = 0; d < D; ++d) {
            const float x = xs[d];
            const float y = fmaf(x, s_a[d], 4.0f);
            int t = __float2int_rd(y);
            t = min(NB - 1, max(0, t));
            const float2 ep = s_ep[d * NB + t];
            const int b = t + (int)(x >= ep.y) - (int)(x < ep.x);
            const float pb = s_p[d * NB + b];
            if (d & 1) pr1 *= pb; else pr0 *= pb;
        }
        out[row] = pr0 * pr1;
    }
}

extern "C" void kernel_launch(void* const* d_in, const int* in_sizes, int n_in,
                              void* d_out, int out_size)
{
    const float* inp   = (const float*)d_in[0];   // [B, 16] fp32
    const float* freq  = (const float*)d_in[1];   // [8, 16] fp32
    const float* edges = (const float*)d_in[2];   // [9, 16] fp32
    float* out = (float*)d_out;                   // [B] fp32

    const int nrows = out_size;
    const int rows_per_block = TPB * RPT;
    const int grid = (nrows + rows_per_block - 1) / rows_per_block;
    hist_kernel<<<grid, TPB>>>(inp, freq, edges, out, nrows);
}